// round 3
// baseline (speedup 1.0000x reference)
#include <cuda_runtime.h>
#include <cstdint>

#define TOK    16384
#define DIM    2048
#define NE     16
#define BT     128
#define NTHR   512
#define TB     4          // tokens per batch
#define NBATCH 32         // BT/TB

#define XSTAGE_B 32768u   // bytes per x stage (4 tok * 8KB)
#define PBUF_F   24576    // float offset of partial buffers (after 3 x-stages)
#define PSTAGE_F 4224     // 64 (t,e) * 66 (64 dpr + pad)
#define LS_F     (PBUF_F + 2*PSTAGE_F)     // 33024
#define SMEM_FLOATS (LS_F + 128*17)        // 35200
#define SMEM_BYTES  (SMEM_FLOATS * 4)      // 140800

__device__ __forceinline__ uint32_t smem_u32(const void* p) {
    uint32_t a;
    asm("{ .reg .u64 t; cvta.to.shared.u64 t, %1; cvt.u32.u64 %0, t; }" : "=r"(a) : "l"(p));
    return a;
}
__device__ __forceinline__ uint32_t sw128(uint32_t o) { return o ^ ((o >> 3) & 0x70u); }

#define CP_ASYNC16(saddr, gptr) \
    asm volatile("cp.async.cg.shared.global [%0], [%1], 16;" :: "r"(saddr), "l"(gptr))
#define CP_COMMIT() asm volatile("cp.async.commit_group;" ::: "memory")
#define CP_WAIT1()  asm volatile("cp.async.wait_group 1;" ::: "memory")
#define CP_WAIT0()  asm volatile("cp.async.wait_group 0;" ::: "memory")

#define MUL2(c, a, b) asm("mul.rn.f32x2 %0, %1, %2;"     : "=l"(c) : "l"(a), "l"(b))
#define FMA2(c, a, b) asm("fma.rn.f32x2 %0, %1, %2, %0;" : "+l"(c) : "l"(a), "l"(b))
#define LDSV2(a, b, addr) \
    asm volatile("ld.shared.v2.b64 {%0, %1}, [%2];" : "=l"(a), "=l"(b) : "r"(addr))
#define STS32(addr, v) asm volatile("st.shared.f32 [%0], %1;" :: "r"(addr), "f"(v))
#define LDS32(v, addr) asm volatile("ld.shared.f32 %0, [%1];" : "=f"(v) : "r"(addr))

__global__ void __launch_bounds__(NTHR, 1)
gating_moe_kernel(const float* __restrict__ x,
                  const float* __restrict__ noise,
                  const float* __restrict__ W,
                  const float* __restrict__ b,
                  float* __restrict__ out)
{
    extern __shared__ float sm[];
    const uint32_t sb   = smem_u32(sm);
    const int tid  = threadIdx.x;
    const int lane = tid & 31;
    const int wid  = tid >> 5;
    const int eg   = lane & 3;          // expert group (4 experts each), broadcast lanes
    const int dpl  = (lane >> 2) & 7;   // d-partition low bits
    const int dp   = wid * 8 + dpl;     // d-partition 0..127 -> dims [dp*16, dp*16+16)
    const int tok0 = blockIdx.x * BT;

    // ---- W resident in registers: 4 experts x 16 dims = 32 f32x2 pairs ----
    unsigned long long w[4][8];
    #pragma unroll
    for (int el = 0; el < 4; el++) {
        const ulonglong2* wp = (const ulonglong2*)(W + (size_t)(eg * 4 + el) * DIM + dp * 16);
        #pragma unroll
        for (int j4 = 0; j4 < 4; j4++) {
            ulonglong2 v = wp[j4];
            w[el][2 * j4]     = v.x;
            w[el][2 * j4 + 1] = v.y;
        }
    }

    // swizzled x LDS offsets (within one 8KB token row)
    uint32_t xoff[4];
    #pragma unroll
    for (int j4 = 0; j4 < 4; j4++)
        xoff[j4] = sw128((uint32_t)(dp * 64 + j4 * 16));

    // cp.async chunk offsets: chunk = tid + 512k -> (tok_local, dvec); same byte
    // offset in global (unswizzled) and smem (swizzled)
    uint32_t cu[4];
    #pragma unroll
    for (int k = 0; k < 4; k++) {
        int ch = tid + NTHR * k;
        cu[k] = (uint32_t)((ch >> 9) * 8192 + (ch & 511) * 16);
    }

    auto prefetch = [&](int bb, int s) {
        const uint32_t base = sb + (uint32_t)s * XSTAGE_B;
        const char* gbase = (const char*)(x + (size_t)(tok0 + bb * TB) * DIM);
        #pragma unroll
        for (int k = 0; k < 4; k++)
            CP_ASYNC16(base + sw128(cu[k]), gbase + cu[k]);
    };

    prefetch(0, 0); CP_COMMIT();
    prefetch(1, 1); CP_COMMIT();

    const uint32_t pb0 = sb + PBUF_F * 4;
    const uint32_t lsb = sb + LS_F * 4;

    for (int bb = 0; bb < NBATCH; bb++) {
        if (bb < NBATCH - 1) { CP_WAIT1(); } else { CP_WAIT0(); }
        __syncthreads();
        if (bb + 2 < NBATCH) { prefetch(bb + 2, (bb + 2) % 3); CP_COMMIT(); }

        // ---- reduce previous batch's partials -> Ls ----
        if (bb > 0) {
            const uint32_t buf = pb0 + (uint32_t)(((bb - 1) & 1) * PSTAGE_F) * 4;
            const int te = tid >> 3, sub = tid & 7;
            const uint32_t ra = buf + (uint32_t)(te * 66 + sub * 8) * 4;
            float r = 0.f;
            #pragma unroll
            for (int k = 0; k < 8; k++) { float v; LDS32(v, ra + k * 4); r += v; }
            r += __shfl_xor_sync(~0u, r, 1);
            r += __shfl_xor_sync(~0u, r, 2);
            r += __shfl_xor_sync(~0u, r, 4);
            if (sub == 0)
                STS32(lsb + (uint32_t)((((bb - 1) * TB + (te >> 4)) * 17 + (te & 15))) * 4, r);
        }

        // ---- compute batch: 4 tokens x 4 experts x 16 dims ----
        unsigned long long acc[TB][4];
        const uint32_t xs = sb + (uint32_t)(bb % 3) * XSTAGE_B;
        #pragma unroll
        for (int t = 0; t < TB; t++) {
            unsigned long long xp[8];
            const uint32_t ta = xs + (uint32_t)t * 8192;
            #pragma unroll
            for (int j4 = 0; j4 < 4; j4++)
                LDSV2(xp[2 * j4], xp[2 * j4 + 1], ta + xoff[j4]);
            #pragma unroll
            for (int el = 0; el < 4; el++) {
                MUL2(acc[t][el], xp[0], w[el][0]);
                #pragma unroll
                for (int j = 1; j < 8; j++)
                    FMA2(acc[t][el], xp[j], w[el][j]);
            }
        }

        // ---- flush partials: halves add + 1-level shfl + STS ----
        const uint32_t buf = pb0 + (uint32_t)((bb & 1) * PSTAGE_F) * 4;
        #pragma unroll
        for (int t = 0; t < TB; t++) {
            #pragma unroll
            for (int el = 0; el < 4; el++) {
                float lo = __uint_as_float((unsigned)(acc[t][el] & 0xffffffffULL));
                float hi = __uint_as_float((unsigned)(acc[t][el] >> 32));
                float s = lo + hi;
                s += __shfl_xor_sync(~0u, s, 4);
                if (!(lane & 4)) {
                    int te = t * 16 + eg * 4 + el;
                    STS32(buf + (uint32_t)(te * 66 + wid * 4 + (dpl >> 1)) * 4, s);
                }
            }
        }
    }

    __syncthreads();
    // final reduce (batch 31)
    {
        const uint32_t buf = pb0 + (uint32_t)(((NBATCH - 1) & 1) * PSTAGE_F) * 4;
        const int te = tid >> 3, sub = tid & 7;
        const uint32_t ra = buf + (uint32_t)(te * 66 + sub * 8) * 4;
        float r = 0.f;
        #pragma unroll
        for (int k = 0; k < 8; k++) { float v; LDS32(v, ra + k * 4); r += v; }
        r += __shfl_xor_sync(~0u, r, 1);
        r += __shfl_xor_sync(~0u, r, 2);
        r += __shfl_xor_sync(~0u, r, 4);
        if (sub == 0)
            STS32(lsb + (uint32_t)((((NBATCH - 1) * TB + (te >> 4)) * 17 + (te & 15))) * 4, r);
    }
    __syncthreads();

    // ---- epilogue: bias + noise + top-2 + 2-way softmax + dense scatter ----
    if (tid < BT) {
        const int gtok = tok0 + tid;
        const float4* nz = (const float4*)(noise + (size_t)gtok * NE);
        float4 n0 = nz[0], n1 = nz[1], n2 = nz[2], n3 = nz[3];
        const float4* bb4 = (const float4*)b;
        float4 b0 = bb4[0], b1 = bb4[1], b2 = bb4[2], b3 = bb4[3];

        float nn[16] = {n0.x, n0.y, n0.z, n0.w, n1.x, n1.y, n1.z, n1.w,
                        n2.x, n2.y, n2.z, n2.w, n3.x, n3.y, n3.z, n3.w};
        float bv[16] = {b0.x, b0.y, b0.z, b0.w, b1.x, b1.y, b1.z, b1.w,
                        b2.x, b2.y, b2.z, b2.w, b3.x, b3.y, b3.z, b3.w};

        float v[16];
        #pragma unroll
        for (int e = 0; e < 16; e++) {
            float l;
            LDS32(l, lsb + (uint32_t)(tid * 17 + e) * 4);
            v[e] = l + bv[e] + 0.1f * nn[e];
        }

        float v1 = -1e30f, v2 = -1e30f;
        int   i1 = -1,     i2 = -1;
        #pragma unroll
        for (int e = 0; e < 16; e++) {
            float val = v[e];
            if (val > v1)      { v2 = v1; i2 = i1; v1 = val; i1 = e; }
            else if (val > v2) { v2 = val; i2 = e; }
        }

        float ew  = expf(v2 - v1);
        float inv = 1.0f / (1.0f + ew);
        float w1  = inv;
        float w2  = ew * inv;

        float o[16];
        #pragma unroll
        for (int e = 0; e < 16; e++)
            o[e] = (e == i1) ? w1 : ((e == i2) ? w2 : 0.0f);

        float4* op = (float4*)(out + (size_t)gtok * NE);
        op[0] = make_float4(o[0],  o[1],  o[2],  o[3]);
        op[1] = make_float4(o[4],  o[5],  o[6],  o[7]);
        op[2] = make_float4(o[8],  o[9],  o[10], o[11]);
        op[3] = make_float4(o[12], o[13], o[14], o[15]);
    }
}

extern "C" void kernel_launch(void* const* d_in, const int* in_sizes, int n_in,
                              void* d_out, int out_size)
{
    const float* x     = (const float*)d_in[0];
    const float* noise = (const float*)d_in[1];
    const float* W     = (const float*)d_in[2];
    const float* b     = (const float*)d_in[3];
    float* out = (float*)d_out;

    cudaFuncSetAttribute(gating_moe_kernel,
                         cudaFuncAttributeMaxDynamicSharedMemorySize, SMEM_BYTES);
    gating_moe_kernel<<<TOK / BT, NTHR, SMEM_BYTES>>>(x, noise, W, b, out);
}